// round 13
// baseline (speedup 1.0000x reference)
#include <cuda_runtime.h>
#include <cstdint>

// Problem constants
#define B_       8192
#define NROW     40
#define FDIM     256
#define NF       (NROW*FDIM)            // 10240
#define TOTROWS  (B_*NROW)              // 327680
#define TOTELEM  ((size_t)TOTROWS*FDIM) // 83,886,080
#define EPS_     1e-5f

// GEMM tiling: CTA 128(M) x 128(N), KT=32, 8 stages, 256 threads
#define NSTG 8
#define ZCTAS (B_/2)    // 4096 z-CTAs (2 batches each)

// Scratch (device-static: no allocations allowed)
// g_z: fragment layout [RT=row/16][ktG=k/8][lane=g*4+t] x float4(v0,v2,v1,v3)
__device__ float g_z[TOTELEM];
__device__ float g_y[TOTELEM];          // row-major Y
// g_Wf: fragment layout [ktG][n8][lane] x float2
__device__ float g_Wf[FDIM*FDIM];
__device__ float g_sum[NF];
__device__ float g_sq[NF];
__device__ float g_scale[NF];
__device__ float g_shift[NF];

__device__ __forceinline__ float to_tf32(float x){
    float r;
    asm("cvt.rna.tf32.f32 %0, %1;" : "=f"(r) : "f"(x));
    return r;
}

__device__ __forceinline__ void cpa16(void* smem_dst, const void* gsrc){
    unsigned d = (unsigned)__cvta_generic_to_shared(smem_dst);
    asm volatile("cp.async.cg.shared.global [%0], [%1], 16;" :: "r"(d), "l"(gsrc));
}

__device__ __forceinline__ void mma_tf32(float* c, const unsigned* a, const unsigned* b){
    asm volatile(
        "mma.sync.aligned.m16n8k8.row.col.f32.tf32.tf32.f32 "
        "{%0,%1,%2,%3}, {%4,%5,%6,%7}, {%8,%9}, {%0,%1,%2,%3};\n"
        : "+f"(c[0]), "+f"(c[1]), "+f"(c[2]), "+f"(c[3])
        : "r"(a[0]), "r"(a[1]), "r"(a[2]), "r"(a[3]), "r"(b[0]), "r"(b[1]));
}

// packed f32x2 FMA (FFMA2) — PTX-only
__device__ __forceinline__ void fma2(unsigned long long& c, unsigned long long a,
                                     unsigned long long b){
    asm("fma.rn.f32x2 %0, %1, %2, %0;" : "+l"(c) : "l"(a), "l"(b));
}
__device__ __forceinline__ unsigned long long bcast2(float a){
    unsigned long long r;
    asm("mov.b64 %0, {%1, %1};" : "=l"(r) : "f"(a));
    return r;
}
__device__ __forceinline__ float2 unpk2(unsigned long long v){
    float2 f;
    asm("mov.b64 {%0, %1}, %2;" : "=f"(f.x), "=f"(f.y) : "l"(v));
    return f;
}

// ---------------------------------------------------------------------------
// K1: z = adj_blk @ inp (fragment layout), 2 batches per CTA over 4096 CTAs.
// CTAs >= ZCTAS do the W-fragment transform + stat zeroing (former k_prep).
__global__ __launch_bounds__(256) void k_z(const float* __restrict__ inp,
                                           const float* __restrict__ adj,
                                           const float* __restrict__ W){
    int bc = blockIdx.x;
    if (bc >= ZCTAS){
        int i = (bc - ZCTAS) * 256 + threadIdx.x;    // 0..65535
        int lane = i & 31;
        int n8   = (i >> 5) & 31;
        int ktG  = i >> 10;
        int g = lane >> 2, t = lane & 3;
        float b0 = to_tf32(W[(ktG*8 + t    )*FDIM + n8*8 + g]);
        float b1 = to_tf32(W[(ktG*8 + t + 4)*FDIM + n8*8 + g]);
        ((float2*)g_Wf)[i] = make_float2(b0, b1);
        if (i < NF){ g_sum[i] = 0.f; g_sq[i] = 0.f; }
        return;
    }

    int sub = threadIdx.x >> 7;      // batch within CTA
    int cp  = threadIdx.x & 127;
    int ktG = cp >> 2, t = cp & 3;
    int b   = bc*2 + sub;

    __shared__ float sadj[2][NROW][NROW];
    for (int i = threadIdx.x; i < 2*NROW*NROW; i += 256){
        int bb = i / (NROW*NROW);
        int j  = i % (NROW*NROW);
        sadj[bb][j/NROW][j%NROW] = adj[(size_t)(bc*2+bb)*NROW*NROW + j];
    }
    __syncthreads();

    int c0 = ktG*8 + t;
    unsigned long long x[NROW];
    const float* ip = inp + (size_t)b*NROW*FDIM + c0;
    #pragma unroll
    for (int j = 0; j < NROW; j++){
        float lo = ip[j*FDIM];
        float hi = ip[j*FDIM + 4];
        asm("mov.b64 %0, {%1, %2};" : "=l"(x[j]) : "f"(lo), "f"(hi));
    }

    int growb = b * NROW;
    #pragma unroll
    for (int r = 0; r < NROW; r++){
        int s = (r/10)*10;
        unsigned long long acc = 0;
        #pragma unroll
        for (int j = 0; j < 10; j++)
            fma2(acc, bcast2(sadj[sub][r][s+j]), x[s+j]);
        float2 f = unpk2(acc);
        float2 o = make_float2(to_tf32(f.x), to_tf32(f.y));
        int grow = growb + r;
        int RT = grow >> 4, lr = grow & 15, g = lr & 7;
        size_t fi = (((size_t)RT*32 + ktG)*32 + (g*4 + t))*4 + ((lr >> 3) << 1);
        *(float2*)(g_z + fi) = o;
    }
}

// ---------------------------------------------------------------------------
// K2: Y = Z @ W (tf32 mma.sync, fragment-layout smem) with fused batch-stat
// accumulation in the epilogue (smem pre-reduce -> global atomics).
__global__ __launch_bounds__(256, 2) void k_mm(){
    __shared__ union {
        struct { float A[2][4096]; float B[4096]; } mm;     // 48 KB
        struct { float sum[40*128]; float sq[40*128]; } st; // 40 KB
    } smu;

    int tid = threadIdx.x;
    int bid = blockIdx.x;
    int nb  = bid & 1;               // adjacent N-halves -> z L2 reuse
    int mb  = bid >> 1;
    int RTb = mb * 8;
    size_t rowbase = (size_t)mb * 128;
    int n0  = nb * 128;
    int lane = tid & 31, warp = tid >> 5;
    int wm = warp >> 1, wn = warp & 1;
    int gq = lane >> 2, tq = lane & 3;

    float acc[2][8][4];
    #pragma unroll
    for (int mt = 0; mt < 2; mt++)
        #pragma unroll
        for (int nt = 0; nt < 8; nt++)
            #pragma unroll
            for (int v = 0; v < 4; v++) acc[mt][nt][v] = 0.f;

    auto cpA = [&](int s, int buf){
        #pragma unroll
        for (int h = 0; h < 4; h++){
            int q  = tid + h*256;          // 0..1023 16B-units
            int rt = q >> 7;
            int u  = (q & 127) * 4;
            cpa16(&smu.mm.A[buf][rt*512 + u],
                  g_z + ((size_t)(RTb + rt)*32 + s*4)*128 + u);
        }
    };
    float4 rb[4];
    auto ldB = [&](int s){
        #pragma unroll
        for (int h = 0; h < 4; h++){
            int q   = tid + h*256;
            int ktg = q >> 8;
            int u   = (q & 255) * 4;
            rb[h] = *(const float4*)(g_Wf + ((size_t)(s*4 + ktg)*32 + nb*16)*64 + u);
        }
    };
    auto stB = [&](){
        #pragma unroll
        for (int h = 0; h < 4; h++){
            int q = tid + h*256;
            int ktg = q >> 8;
            int u   = (q & 255) * 4;
            *(float4*)&smu.mm.B[ktg*1024 + u] = rb[h];
        }
    };

    ldB(0);
    cpA(0, 0);
    asm volatile("cp.async.commit_group;");

    for (int s = 0; s < NSTG; s++){
        int cur = s & 1;
        asm volatile("cp.async.wait_group 0;" ::: "memory");
        __syncthreads();
        stB();
        if (s + 1 < NSTG){
            cpA(s + 1, cur ^ 1);
            asm volatile("cp.async.commit_group;");
        }
        __syncthreads();
        if (s + 1 < NSTG) ldB(s + 1);

        #pragma unroll
        for (int k8 = 0; k8 < 4; k8++){
            unsigned a[2][4];
            #pragma unroll
            for (int mt = 0; mt < 2; mt++){
                int rt = wm*2 + mt;
                float4 fa = *(const float4*)&smu.mm.A[cur][rt*512 + k8*128 + lane*4];
                a[mt][0] = __float_as_uint(fa.x);
                a[mt][1] = __float_as_uint(fa.z);
                a[mt][2] = __float_as_uint(fa.y);
                a[mt][3] = __float_as_uint(fa.w);
            }
            #pragma unroll
            for (int nt = 0; nt < 8; nt++){
                float2 fb = *(const float2*)&smu.mm.B[(k8*16 + wn*8 + nt)*64 + lane*2];
                unsigned bb[2] = { __float_as_uint(fb.x), __float_as_uint(fb.y) };
                mma_tf32(acc[0][nt], a[0], bb);
                mma_tf32(acc[1][nt], a[1], bb);
            }
        }
    }

    // ---- Epilogue: y stores + fused stat reduction ----
    __syncthreads();                 // mainloop smem reads complete
    for (int i = tid; i < 40*128; i += 256){
        smu.st.sum[i] = 0.f;
        smu.st.sq[i]  = 0.f;
    }
    __syncthreads();

    #pragma unroll
    for (int mt = 0; mt < 2; mt++){
        int r  = wm*32 + mt*16 + gq;
        int fr0 = (int)((rowbase + r) % 40);
        int fr1 = fr0 + 8; if (fr1 >= 40) fr1 -= 40;
        #pragma unroll
        for (int nt = 0; nt < 8; nt++){
            int cl = wn*64 + nt*8 + 2*tq;
            float v0 = acc[mt][nt][0], v1 = acc[mt][nt][1];
            float v2 = acc[mt][nt][2], v3 = acc[mt][nt][3];
            *(float2*)(g_y + (rowbase + r    )*FDIM + n0 + cl) = make_float2(v0, v1);
            *(float2*)(g_y + (rowbase + r + 8)*FDIM + n0 + cl) = make_float2(v2, v3);
            atomicAdd(&smu.st.sum[fr0*128 + cl    ], v0);
            atomicAdd(&smu.st.sum[fr0*128 + cl + 1], v1);
            atomicAdd(&smu.st.sum[fr1*128 + cl    ], v2);
            atomicAdd(&smu.st.sum[fr1*128 + cl + 1], v3);
            atomicAdd(&smu.st.sq [fr0*128 + cl    ], v0*v0);
            atomicAdd(&smu.st.sq [fr0*128 + cl + 1], v1*v1);
            atomicAdd(&smu.st.sq [fr1*128 + cl    ], v2*v2);
            atomicAdd(&smu.st.sq [fr1*128 + cl + 1], v3*v3);
        }
    }
    __syncthreads();

    for (int i = tid; i < 40*128; i += 256){
        int fr = i >> 7, cl = i & 127;
        atomicAdd(&g_sum[fr*FDIM + n0 + cl], smu.st.sum[i]);
        atomicAdd(&g_sq [fr*FDIM + n0 + cl], smu.st.sq[i]);
    }
}

// ---------------------------------------------------------------------------
// K3: fold mean/var/gamma/beta -> per-feature scale & shift.
__global__ void k_final(const float* __restrict__ gamma,
                        const float* __restrict__ beta){
    int q = blockIdx.x * 256 + threadIdx.x;   // 0..10239
    float inv = 1.f / (float)B_;
    float mean = g_sum[q] * inv;
    float var  = g_sq[q] * inv - mean*mean;
    int i = q / (10*FDIM);
    float sc = rsqrtf(var + EPS_) * gamma[i*NF + q];
    float bs = beta[q] + beta[NF + q] + beta[2*NF + q] + beta[3*NF + q];
    g_scale[q] = sc;
    g_shift[q] = bs - mean*sc;
}

// ---------------------------------------------------------------------------
// K4: streaming normalize (float4).
__global__ __launch_bounds__(256) void k_norm(float* __restrict__ out){
    size_t idx = (size_t)blockIdx.x * 256 + threadIdx.x;
    int q4 = (int)(idx % (NF/4));
    float4 v  = ((const float4*)g_y)[idx];
    float4 sc = ((const float4*)g_scale)[q4];
    float4 sh = ((const float4*)g_shift)[q4];
    float4 o;
    o.x = v.x*sc.x + sh.x;
    o.y = v.y*sc.y + sh.y;
    o.z = v.z*sc.z + sh.z;
    o.w = v.w*sc.w + sh.w;
    ((float4*)out)[idx] = o;
}

// ---------------------------------------------------------------------------
extern "C" void kernel_launch(void* const* d_in, const int* in_sizes, int n_in,
                              void* d_out, int out_size){
    const float* inp   = (const float*)d_in[0];
    const float* adj   = (const float*)d_in[1];
    const float* W     = (const float*)d_in[2];
    const float* gamma = (const float*)d_in[3];
    const float* beta  = (const float*)d_in[4];
    float* out = (float*)d_out;

    k_z    <<<ZCTAS + 256, 256>>>(inp, adj, W);
    k_mm   <<<(TOTROWS/128)*2, 256>>>();
    k_final<<<NF/256, 256>>>(gamma, beta);
    k_norm <<<(unsigned)(TOTELEM/4/256), 256>>>(out);
}

// round 15
// speedup vs baseline: 1.5946x; 1.5946x over previous
#include <cuda_runtime.h>
#include <cstdint>

// Problem constants
#define B_       8192
#define NROW     40
#define FDIM     256
#define NF       (NROW*FDIM)            // 10240
#define TOTROWS  (B_*NROW)              // 327680
#define TOTELEM  ((size_t)TOTROWS*FDIM) // 83,886,080
#define EPS_     1e-5f

// GEMM tiling (R3-proven): CTA 128x128, KT=16, double-buffered, 256 thr
#define KT   16
#define NSTAGE (FDIM/KT)   // 16

// k_blk: 16 batches per CTA, 512 threads
#define BLKB 16

// Scratch (device-static: no allocations allowed)
__device__ float g_s[TOTELEM];      // S = X @ W (row-major)
__device__ float g_y[TOTELEM];      // y = blockdiag(adj) @ S
__device__ float g_Wt[FDIM*FDIM];   // W rounded to tf32 (row-major [k][n])
__device__ float g_sum[NF];
__device__ float g_sq[NF];
__device__ float g_scale[NF];
__device__ float g_shift[NF];

__device__ __forceinline__ float to_tf32(float x){
    float r;
    asm("cvt.rna.tf32.f32 %0, %1;" : "=f"(r) : "f"(x));
    return r;
}

__device__ __forceinline__ void cpa16(void* smem_dst, const void* gsrc){
    unsigned d = (unsigned)__cvta_generic_to_shared(smem_dst);
    asm volatile("cp.async.cg.shared.global [%0], [%1], 16;" :: "r"(d), "l"(gsrc));
}

__device__ __forceinline__ void mma_tf32(float* c, const unsigned* a, const unsigned* b){
    asm volatile(
        "mma.sync.aligned.m16n8k8.row.col.f32.tf32.tf32.f32 "
        "{%0,%1,%2,%3}, {%4,%5,%6,%7}, {%8,%9}, {%0,%1,%2,%3};\n"
        : "+f"(c[0]), "+f"(c[1]), "+f"(c[2]), "+f"(c[3])
        : "r"(a[0]), "r"(a[1]), "r"(a[2]), "r"(a[3]), "r"(b[0]), "r"(b[1]));
}

// ---------------------------------------------------------------------------
// K0: W -> tf32 (row-major), zero stat accumulators (re-zero every replay).
__global__ void k_prep(const float* __restrict__ W){
    int i = blockIdx.x * 256 + threadIdx.x;
    if (i < FDIM*FDIM) g_Wt[i] = to_tf32(W[i]);
    if (i < NF){ g_sum[i] = 0.f; g_sq[i] = 0.f; }
}

// ---------------------------------------------------------------------------
// K1: S = X @ W  (tf32 mma.sync). A-fragments rna-rounded after LDS.
// 1D grid, nb = bid&1 so both N-halves of an M-tile are schedule-adjacent
// (second X read hits L2).
__global__ __launch_bounds__(256) void k_gemm(const float* __restrict__ X){
    __shared__ float sA[2][128][20];   // pad 20: conflict-free A lds
    __shared__ float sB[2][KT][136];   // pad 136: conflict-free B lds

    int tid  = threadIdx.x;
    int bid  = blockIdx.x;
    int nb   = bid & 1;
    int mb   = bid >> 1;
    size_t rowbase = (size_t)mb * 128;
    int n0   = nb * 128;
    int lane = tid & 31, warp = tid >> 5;
    int wm   = warp >> 1, wn = warp & 1;
    int g    = lane >> 2, t = lane & 3;

    int la_row = tid >> 2;            // 0..63 (+64)
    int la_col = (tid & 3) * 4;       // 0,4,8,12
    int lb_row = tid >> 5;            // 0..7 (+8)
    int lb_col = (tid & 31) * 4;      // 0..124

    float acc[2][8][4];
    #pragma unroll
    for (int mt = 0; mt < 2; mt++)
        #pragma unroll
        for (int nt = 0; nt < 8; nt++)
            #pragma unroll
            for (int v = 0; v < 4; v++) acc[mt][nt][v] = 0.f;

    auto loadStage = [&](int s, int buf){
        int k0 = s * KT;
        cpa16(&sA[buf][la_row   ][la_col], X + (rowbase + la_row     )*FDIM + k0 + la_col);
        cpa16(&sA[buf][la_row+64][la_col], X + (rowbase + la_row + 64)*FDIM + k0 + la_col);
        cpa16(&sB[buf][lb_row   ][lb_col], g_Wt + (size_t)(k0 + lb_row    )*FDIM + n0 + lb_col);
        cpa16(&sB[buf][lb_row+8 ][lb_col], g_Wt + (size_t)(k0 + lb_row + 8)*FDIM + n0 + lb_col);
    };

    loadStage(0, 0);
    asm volatile("cp.async.commit_group;");

    for (int s = 0; s < NSTAGE; s++){
        int cur = s & 1;
        asm volatile("cp.async.wait_all;" ::: "memory");
        __syncthreads();
        if (s + 1 < NSTAGE){
            loadStage(s + 1, cur ^ 1);
            asm volatile("cp.async.commit_group;");
        }
        #pragma unroll
        for (int k8 = 0; k8 < KT/8; k8++){
            unsigned a[2][4], bf[8][2];
            int kc = k8*8 + t;
            #pragma unroll
            for (int mt = 0; mt < 2; mt++){
                int r0 = wm*32 + mt*16 + g;
                a[mt][0] = __float_as_uint(to_tf32(sA[cur][r0  ][kc  ]));
                a[mt][1] = __float_as_uint(to_tf32(sA[cur][r0+8][kc  ]));
                a[mt][2] = __float_as_uint(to_tf32(sA[cur][r0  ][kc+4]));
                a[mt][3] = __float_as_uint(to_tf32(sA[cur][r0+8][kc+4]));
            }
            #pragma unroll
            for (int nt = 0; nt < 8; nt++){
                int cc = wn*64 + nt*8 + g;
                bf[nt][0] = __float_as_uint(sB[cur][kc  ][cc]);
                bf[nt][1] = __float_as_uint(sB[cur][kc+4][cc]);
            }
            #pragma unroll
            for (int mt = 0; mt < 2; mt++)
                #pragma unroll
                for (int nt = 0; nt < 8; nt++)
                    mma_tf32(acc[mt][nt], a[mt], bf[nt]);
        }
        __syncthreads();
    }

    // Epilogue: write S (float2)
    #pragma unroll
    for (int mt = 0; mt < 2; mt++){
        int r = wm*32 + mt*16 + g;
        #pragma unroll
        for (int nt = 0; nt < 8; nt++){
            int c = n0 + wn*64 + nt*8 + 2*t;
            float2 v0 = make_float2(acc[mt][nt][0], acc[mt][nt][1]);
            float2 v1 = make_float2(acc[mt][nt][2], acc[mt][nt][3]);
            *(float2*)(g_s + (rowbase + r    )*FDIM + c) = v0;
            *(float2*)(g_s + (rowbase + r + 8)*FDIM + c) = v1;
        }
    }
}

// ---------------------------------------------------------------------------
// K2: y = blockdiag(adj) @ S, with fused batch statistics.
// CTA = 16 whole batches, 512 threads: tid -> (f = tid%256, rh = tid/256).
// Thread owns feature column f, rows rh*20..rh*20+19 (2 diag blocks),
// accumulating sum/sq over its 16 batches in registers; one spread
// global-atomic flush at the end.
__global__ __launch_bounds__(512) void k_blk(const float* __restrict__ adj){
    __shared__ float sadj[BLKB][4][10][10];   // 25.6 KB

    int tid = threadIdx.x;
    int f   = tid & 255;
    int rh  = tid >> 8;            // 0/1
    int b0  = blockIdx.x * BLKB;

    for (int i = tid; i < BLKB*400; i += 512){
        int bb  = i / 400;
        int rem = i % 400;
        int blk = rem / 100;
        int ri  = (rem / 10) % 10;
        int jj  = rem % 10;
        sadj[bb][blk][ri][jj] =
            adj[(size_t)(b0 + bb)*(NROW*NROW) + (size_t)(blk*10 + ri)*NROW + blk*10 + jj];
    }
    __syncthreads();

    int rowoff = rh * 20;          // rows rowoff..rowoff+19, blocks 2rh, 2rh+1

    float sum[20], sq[20];
    #pragma unroll
    for (int i = 0; i < 20; i++){ sum[i] = 0.f; sq[i] = 0.f; }

    for (int bb = 0; bb < BLKB; bb++){
        size_t base = ((size_t)(b0 + bb)*NROW + rowoff)*FDIM + f;
        const float* Sp = g_s + base;
        float* yp = g_y + base;

        float x[20];
        #pragma unroll
        for (int j = 0; j < 20; j++) x[j] = Sp[j*FDIM];

        #pragma unroll
        for (int pp = 0; pp < 2; pp++){
            int blk = rh*2 + pp;
            #pragma unroll
            for (int r = 0; r < 10; r++){
                float a = 0.f;
                #pragma unroll
                for (int j = 0; j < 10; j++)
                    a += sadj[bb][blk][r][j] * x[pp*10 + j];
                int ri = pp*10 + r;
                yp[ri*FDIM] = a;
                sum[ri] += a;
                sq[ri]  += a*a;
            }
        }
    }

    // flush partials (spread addresses; consecutive f per warp -> coalesced REDG)
    #pragma unroll
    for (int ri = 0; ri < 20; ri++){
        atomicAdd(&g_sum[(rowoff + ri)*FDIM + f], sum[ri]);
        atomicAdd(&g_sq [(rowoff + ri)*FDIM + f], sq[ri]);
    }
}

// ---------------------------------------------------------------------------
// K3: fold mean/var/gamma/beta -> per-feature scale & shift.
// out = y*scale + (betaSum - mean*scale)
__global__ void k_final(const float* __restrict__ gamma,
                        const float* __restrict__ beta){
    int q = blockIdx.x * 256 + threadIdx.x;   // 0..10239
    float inv = 1.f / (float)B_;
    float mean = g_sum[q] * inv;
    float var  = g_sq[q] * inv - mean*mean;
    int i = q / (10*FDIM);                    // crop owning row r = q/256
    float sc = rsqrtf(var + EPS_) * gamma[i*NF + q];
    float bs = beta[q] + beta[NF + q] + beta[2*NF + q] + beta[3*NF + q];
    g_scale[q] = sc;
    g_shift[q] = bs - mean*sc;
}

// ---------------------------------------------------------------------------
// K4: streaming normalize (float4).
__global__ __launch_bounds__(256) void k_norm(float* __restrict__ out){
    size_t idx = (size_t)blockIdx.x * 256 + threadIdx.x;  // < 20,971,520
    int q4 = (int)(idx % (NF/4));
    float4 v  = ((const float4*)g_y)[idx];
    float4 sc = ((const float4*)g_scale)[q4];
    float4 sh = ((const float4*)g_shift)[q4];
    float4 o;
    o.x = v.x*sc.x + sh.x;
    o.y = v.y*sc.y + sh.y;
    o.z = v.z*sc.z + sh.z;
    o.w = v.w*sc.w + sh.w;
    ((float4*)out)[idx] = o;
}

// ---------------------------------------------------------------------------
extern "C" void kernel_launch(void* const* d_in, const int* in_sizes, int n_in,
                              void* d_out, int out_size){
    const float* inp   = (const float*)d_in[0];
    const float* adj   = (const float*)d_in[1];
    const float* W     = (const float*)d_in[2];
    const float* gamma = (const float*)d_in[3];
    const float* beta  = (const float*)d_in[4];
    float* out = (float*)d_out;

    k_prep <<<256, 256>>>(W);
    k_gemm <<<(TOTROWS/128)*2, 256>>>(inp);
    k_blk  <<<B_/BLKB, 512>>>(adj);
    k_final<<<NF/256, 256>>>(gamma, beta);
    k_norm <<<(unsigned)(TOTELEM/4/256), 256>>>(out);
}